// round 8
// baseline (speedup 1.0000x reference)
#include <cuda_runtime.h>
#include <cuda_fp16.h>
#include <math.h>
#include <stdint.h>

// ---------------- problem constants ----------------
#define S_    2048
#define D_    2048
#define HID_  5632
#define NH_   32
#define NKV_  8
#define HD_   64
#define KV_   (NKV_*HD_)     // 512
#define NQKV  (D_ + 2*KV_)   // 3072
#define N13   (2*HID_)       // 11264

// ---------------- scratch ----------------
__device__ __half g_h16 [S_*D_];
__device__ float  g_qkv [S_*NQKV];
__device__ __half g_ao16[S_*D_];
__device__ float  g_x1  [S_*D_];
__device__ __half g_h216[S_*D_];
__device__ float  g_p13 [S_*N13];
__device__ __half g_p1h [S_*HID_];
// fp16 transposed weights ([N][K] K-major)
__device__ __half g_wtqkv[NQKV*D_];
__device__ __half g_wto  [D_*D_];
__device__ __half g_wt13 [N13*D_];
__device__ __half g_wt2  [D_*HID_];

// ---------------- helpers ----------------
__device__ __forceinline__ void mma_f16(float* c, const uint32_t* a, uint32_t b0, uint32_t b1) {
    asm volatile(
        "mma.sync.aligned.m16n8k16.row.col.f32.f16.f16.f32 "
        "{%0,%1,%2,%3}, {%4,%5,%6,%7}, {%8,%9}, {%0,%1,%2,%3};"
        : "+f"(c[0]), "+f"(c[1]), "+f"(c[2]), "+f"(c[3])
        : "r"(a[0]), "r"(a[1]), "r"(a[2]), "r"(a[3]), "r"(b0), "r"(b1));
}
__device__ __forceinline__ void ldmatrix4(uint32_t* r, uint32_t addr) {
    asm volatile("ldmatrix.sync.aligned.m8n8.x4.shared.b16 {%0,%1,%2,%3}, [%4];"
                 : "=r"(r[0]), "=r"(r[1]), "=r"(r[2]), "=r"(r[3]) : "r"(addr));
}
__device__ __forceinline__ void cp16(uint32_t s, const void* g) {
    asm volatile("cp.async.cg.shared.global [%0], [%1], 16;" :: "r"(s), "l"(g));
}
__device__ __forceinline__ void cp_commit() { asm volatile("cp.async.commit_group;"); }
__device__ __forceinline__ void cp_wait1()  { asm volatile("cp.async.wait_group 1;"); }

// ---------------- FP16 mma.sync GEMM: CTA 128x256x64, 8 warps (2x4), warp 64x64 ----------------
// C[M,N] = A[M,K](f16) @ Bt[N,K](f16)^T (+res f32).
#define RSTR_B   144        // bytes per smem row (64 halves + 8 pad) -> ldmatrix conflict-free
#define A_BYTES  (128*RSTR_B)   // 18432
#define B_BYTES  (256*RSTR_B)   // 36864
#define STG_B    (A_BYTES + B_BYTES)   // 55296
#define GNS      3
#define GEMM_SMEM (GNS * STG_B)        // 165888

__global__ __launch_bounds__(256) void gemm_f16_kernel(const __half* __restrict__ A,
                                                       const __half* __restrict__ Bt,
                                                       const float* __restrict__ res,
                                                       float* __restrict__ C,
                                                       int M, int N, int K) {
    extern __shared__ __align__(128) char smem[];
    const uint32_t s0 = (uint32_t)__cvta_generic_to_shared(smem);

    const int tid  = threadIdx.x;
    const int lane = tid & 31;
    const int wid  = tid >> 5;
    const int wm   = wid >> 2;   // 0..1  (64 rows each)
    const int wn   = wid & 3;    // 0..3  (64 cols each)
    const int bm   = blockIdx.x * 128;
    const int bn   = blockIdx.y * 256;
    const int NT   = K >> 6;

    // ldmatrix per-lane byte offsets (within a stage)
    uint32_t a_off[4], b_off[4];
    #pragma unroll
    for (int t = 0; t < 4; t++)
        a_off[t] = (uint32_t)(wm * 64 + t * 16 + (lane & 15)) * RSTR_B + (lane >> 4) * 16;
    #pragma unroll
    for (int u = 0; u < 4; u++)
        b_off[u] = A_BYTES + (uint32_t)(wn * 64 + u * 16 + (lane & 7) + ((lane >> 4) * 8)) * RSTR_B
                 + ((lane >> 3) & 1) * 16;

    // global->smem load mapping
    const int arow = tid >> 1;                    // 0..127
    const int acn  = (tid & 1) * 4;               // A chunk base (of 8 16B chunks)
    const __half* Ag = A + (size_t)(bm + arow) * K + acn * 8;
    const __half* Bg = Bt + (size_t)(bn + tid) * K;

    auto load_stage = [&](int kt, int s) {
        uint32_t ab = s0 + s * STG_B;
        const char* ag = (const char*)(Ag + kt * 64);
        uint32_t as = ab + arow * RSTR_B + acn * 16;
        #pragma unroll
        for (int i = 0; i < 4; i++) cp16(as + i * 16, ag + i * 16);
        const char* bg = (const char*)(Bg + kt * 64);
        uint32_t bs = ab + A_BYTES + tid * RSTR_B;
        #pragma unroll
        for (int i = 0; i < 8; i++) cp16(bs + i * 16, bg + i * 16);
    };

    float c[4][8][4];
    #pragma unroll
    for (int t = 0; t < 4; t++)
        #pragma unroll
        for (int n = 0; n < 8; n++)
            #pragma unroll
            for (int i = 0; i < 4; i++) c[t][n][i] = 0.f;

    load_stage(0, 0); cp_commit();
    load_stage(1, 1); cp_commit();

    int stg = 0;
    for (int kt = 0; kt < NT; kt++) {
        cp_wait1();
        __syncthreads();
        int nk = kt + 2;
        int nstg = stg + 2; if (nstg >= 3) nstg -= 3;
        if (nk < NT) load_stage(nk, nstg);
        cp_commit();

        const uint32_t sbase = s0 + stg * STG_B;
        #pragma unroll
        for (int s16 = 0; s16 < 4; s16++) {
            uint32_t af[4][4], bf[4][4];
            #pragma unroll
            for (int t = 0; t < 4; t++) ldmatrix4(af[t], sbase + a_off[t] + s16 * 32);
            #pragma unroll
            for (int u = 0; u < 4; u++) ldmatrix4(bf[u], sbase + b_off[u] + s16 * 32);
            #pragma unroll
            for (int t = 0; t < 4; t++)
                #pragma unroll
                for (int u = 0; u < 4; u++) {
                    mma_f16(c[t][2 * u],     af[t], bf[u][0], bf[u][1]);
                    mma_f16(c[t][2 * u + 1], af[t], bf[u][2], bf[u][3]);
                }
        }
        stg++; if (stg >= 3) stg = 0;
    }

    // epilogue: direct global stores
    const int rr = lane >> 2;
    const int cc = lane & 3;
    #pragma unroll
    for (int t = 0; t < 4; t++) {
        int gr = bm + wm * 64 + t * 16 + rr;
        #pragma unroll
        for (int n = 0; n < 8; n++) {
            int gc = bn + wn * 64 + n * 8 + cc * 2;
            size_t i0 = (size_t)gr * N + gc;
            size_t i1 = i0 + (size_t)8 * N;
            float2 v0 = { c[t][n][0], c[t][n][1] };
            float2 v1 = { c[t][n][2], c[t][n][3] };
            if (res) {
                const float2 r0 = *(const float2*)&res[i0];
                const float2 r1 = *(const float2*)&res[i1];
                v0.x += r0.x; v0.y += r0.y;
                v1.x += r1.x; v1.y += r1.y;
            }
            *(float2*)&C[i0] = v0;
            *(float2*)&C[i1] = v1;
        }
    }
}

// ---------------- weight transpose+convert: W[K][N] f32 -> Wt[N][K] f16 ----------------
__global__ __launch_bounds__(256) void transpose_f16_kernel(const float* __restrict__ in,
                                                            __half* __restrict__ out,
                                                            int K, int N) {
    __shared__ float t[32][33];
    int k0 = blockIdx.y * 32, n0 = blockIdx.x * 32;
    int tx = threadIdx.x, ty = threadIdx.y;   // 32 x 8
    #pragma unroll
    for (int j = 0; j < 4; j++)
        t[ty + j * 8][tx] = in[(size_t)(k0 + ty + j * 8) * N + n0 + tx];
    __syncthreads();
    #pragma unroll
    for (int j = 0; j < 4; j++)
        out[(size_t)(n0 + ty + j * 8) * K + k0 + tx] = __float2half_rn(t[tx][ty + j * 8]);
}

// ---------------- LayerNorm: f32 in, f16 out ----------------
__global__ __launch_bounds__(256) void ln_kernel(const float* __restrict__ x,
                                                 const float* __restrict__ w,
                                                 const float* __restrict__ b,
                                                 __half* __restrict__ out) {
    int row = blockIdx.x;
    const float4* xr = (const float4*)(x + (size_t)row * D_);
    float4 v0 = xr[threadIdx.x * 2 + 0];
    float4 v1 = xr[threadIdx.x * 2 + 1];
    float s  = v0.x + v0.y + v0.z + v0.w + v1.x + v1.y + v1.z + v1.w;
    float ss = v0.x*v0.x + v0.y*v0.y + v0.z*v0.z + v0.w*v0.w
             + v1.x*v1.x + v1.y*v1.y + v1.z*v1.z + v1.w*v1.w;
    #pragma unroll
    for (int o = 16; o; o >>= 1) {
        s  += __shfl_xor_sync(0xffffffffu, s,  o);
        ss += __shfl_xor_sync(0xffffffffu, ss, o);
    }
    __shared__ float sm[18];
    int warp = threadIdx.x >> 5, lane = threadIdx.x & 31;
    if (lane == 0) { sm[warp] = s; sm[8 + warp] = ss; }
    __syncthreads();
    if (threadIdx.x == 0) {
        float S1 = 0.f, S2 = 0.f;
        #pragma unroll
        for (int i = 0; i < 8; i++) { S1 += sm[i]; S2 += sm[8 + i]; }
        float mean = S1 / (float)D_;
        float var  = S2 / (float)D_ - mean * mean;
        sm[16] = mean;
        sm[17] = rsqrtf(var + 1e-5f);
    }
    __syncthreads();
    float mean = sm[16], inv = sm[17];
    const float4* wv = (const float4*)w;
    const float4* bv = (const float4*)b;
    __half2* ov = (__half2*)(out + (size_t)row * D_);
    #pragma unroll
    for (int u = 0; u < 2; u++) {
        int idx = threadIdx.x * 2 + u;
        float4 v = (u == 0) ? v0 : v1;
        float4 W = wv[idx], B = bv[idx];
        float o0 = (v.x - mean) * inv * W.x + B.x;
        float o1 = (v.y - mean) * inv * W.y + B.y;
        float o2 = (v.z - mean) * inv * W.z + B.z;
        float o3 = (v.w - mean) * inv * W.w + B.w;
        ov[idx * 2 + 0] = __floats2half2_rn(o0, o1);
        ov[idx * 2 + 1] = __floats2half2_rn(o2, o3);
    }
}

// ---------------- RoPE on strided layout ----------------
__global__ void rope_kernel(float* __restrict__ x, int H, int stride, int total) {
    int i = blockIdx.x * blockDim.x + threadIdx.x;
    if (i >= total) return;
    int p = i & 31;
    int h = (i >> 5) % H;
    int s = i / (32 * H);
    float freq = exp2f(-(float)p * 0.415241011860920f);
    float ang = (float)s * freq;
    float c, sn;
    sincosf(ang, &sn, &c);
    float* base = x + (size_t)s * stride + h * HD_;
    float xr = base[2 * p], xi = base[2 * p + 1];
    base[2 * p]     = xr * c - xi * sn;
    base[2 * p + 1] = xr * sn + xi * c;
}

// ---------------- Flash attention: strided QKV in, f16 out ----------------
__global__ __launch_bounds__(256) void attn_kernel(const float* __restrict__ Q,
                                                   const float* __restrict__ K,
                                                   const float* __restrict__ V,
                                                   const int* __restrict__ mask,
                                                   __half* __restrict__ O) {
    __shared__ float Ks[64][64];
    __shared__ float Vs[64][64];
    __shared__ float bias[64];
    const int h = blockIdx.y;
    const int kvh = h >> 2;            // N_REP = 4
    const int tid = threadIdx.x;
    const int qi = tid >> 3;
    const int lane8 = tid & 7;
    const int qrow = blockIdx.x * 32 + qi;

    float qreg[8];
    const float* qp = Q + (size_t)qrow * NQKV + h * HD_;
    #pragma unroll
    for (int d = 0; d < 8; d++) qreg[d] = qp[lane8 + 8 * d] * 0.125f;

    float m = -INFINITY, l = 0.f;
    float o[8] = {0.f, 0.f, 0.f, 0.f, 0.f, 0.f, 0.f, 0.f};

    const int rr = tid >> 2;
    const int c4 = (tid & 3) * 16;

    for (int kt = 0; kt < S_; kt += 64) {
        const float* kp = K + (size_t)(kt + rr) * NQKV + kvh * HD_ + c4;
        const float* vp = V + (size_t)(kt + rr) * NQKV + kvh * HD_ + c4;
        __syncthreads();
        #pragma unroll
        for (int u = 0; u < 4; u++) {
            *(float4*)&Ks[rr][c4 + u * 4] = *(const float4*)(kp + u * 4);
            *(float4*)&Vs[rr][c4 + u * 4] = *(const float4*)(vp + u * 4);
        }
        if (tid < 64) bias[tid] = (mask[kt + tid] == 0) ? -1e30f : 0.f;
        __syncthreads();

        #pragma unroll 2
        for (int j = 0; j < 64; j++) {
            float sc = 0.f;
            #pragma unroll
            for (int d = 0; d < 8; d++) sc += qreg[d] * Ks[j][lane8 + 8 * d];
            sc += __shfl_xor_sync(0xffffffffu, sc, 1);
            sc += __shfl_xor_sync(0xffffffffu, sc, 2);
            sc += __shfl_xor_sync(0xffffffffu, sc, 4);
            sc += bias[j];
            if (sc > m) {
                float f = __expf(m - sc);
                m = sc;
                l = l * f + 1.f;
                #pragma unroll
                for (int d = 0; d < 8; d++) o[d] = o[d] * f + Vs[j][lane8 + 8 * d];
            } else {
                float p = __expf(sc - m);
                l += p;
                #pragma unroll
                for (int d = 0; d < 8; d++) o[d] += p * Vs[j][lane8 + 8 * d];
            }
        }
    }
    float inv = 1.f / l;
    __half* op = O + (size_t)qrow * D_ + h * HD_;
    #pragma unroll
    for (int d = 0; d < 8; d++) op[lane8 + 8 * d] = __float2half_rn(o[d] * inv);
}

// ---------------- SiLU(p13[:, :HID]) * p13[:, HID:] -> f16 ----------------
__global__ void silumul_kernel(const float* __restrict__ p13, __half* __restrict__ out, int n4) {
    int i = blockIdx.x * blockDim.x + threadIdx.x;
    if (i >= n4) return;
    int row = i / (HID_ / 4);
    int col = (i % (HID_ / 4)) * 4;
    const float4 a = *(const float4*)&p13[(size_t)row * N13 + col];
    const float4 c = *(const float4*)&p13[(size_t)row * N13 + HID_ + col];
    float o0 = a.x / (1.f + __expf(-a.x)) * c.x;
    float o1 = a.y / (1.f + __expf(-a.y)) * c.y;
    float o2 = a.z / (1.f + __expf(-a.z)) * c.z;
    float o3 = a.w / (1.f + __expf(-a.w)) * c.w;
    __half2* op = (__half2*)(out + (size_t)row * HID_ + col);
    op[0] = __floats2half2_rn(o0, o1);
    op[1] = __floats2half2_rn(o2, o3);
}

// ---------------- launch ----------------
static void gemm(const __half* A, const __half* Bt, const float* res, float* C, int M, int N, int K) {
    dim3 grid(M / 128, N / 256);   // x = M tiles (fast-varying) for L2 reuse of B
    gemm_f16_kernel<<<grid, 256, GEMM_SMEM>>>(A, Bt, res, C, M, N, K);
}
static void wtrans(const float* in, __half* out, int K, int N) {
    transpose_f16_kernel<<<dim3(N / 32, K / 32), dim3(32, 8)>>>(in, out, K, N);
}

extern "C" void kernel_launch(void* const* d_in, const int* in_sizes, int n_in,
                              void* d_out, int out_size) {
    const float* x    = (const float*)d_in[0];
    const int*   mask = (const int*)  d_in[1];
    const float* wq   = (const float*)d_in[2];
    const float* wk   = (const float*)d_in[3];
    const float* wv   = (const float*)d_in[4];
    const float* wo   = (const float*)d_in[5];
    const float* w1   = (const float*)d_in[6];
    const float* w2   = (const float*)d_in[7];
    const float* w3   = (const float*)d_in[8];
    const float* ln1w = (const float*)d_in[9];
    const float* ln1b = (const float*)d_in[10];
    const float* ln2w = (const float*)d_in[11];
    const float* ln2b = (const float*)d_in[12];
    float* out = (float*)d_out;

    static bool attr_done = false;
    if (!attr_done) {
        cudaFuncSetAttribute(gemm_f16_kernel, cudaFuncAttributeMaxDynamicSharedMemorySize, GEMM_SMEM);
        attr_done = true;
    }

    __half *h16, *ao16, *h216, *p1h, *wtqkv, *wto, *wt13, *wt2;
    float *qkv, *x1, *p13;
    cudaGetSymbolAddress((void**)&h16,   g_h16);
    cudaGetSymbolAddress((void**)&qkv,   g_qkv);
    cudaGetSymbolAddress((void**)&ao16,  g_ao16);
    cudaGetSymbolAddress((void**)&x1,    g_x1);
    cudaGetSymbolAddress((void**)&h216,  g_h216);
    cudaGetSymbolAddress((void**)&p13,   g_p13);
    cudaGetSymbolAddress((void**)&p1h,   g_p1h);
    cudaGetSymbolAddress((void**)&wtqkv, g_wtqkv);
    cudaGetSymbolAddress((void**)&wto,   g_wto);
    cudaGetSymbolAddress((void**)&wt13,  g_wt13);
    cudaGetSymbolAddress((void**)&wt2,   g_wt2);

    // weights -> f16, transposed [N][K]; QKV and W1|W3 fused along N
    wtrans(wq, wtqkv,                       D_, D_);
    wtrans(wk, wtqkv + (size_t)D_ * D_,     D_, KV_);
    wtrans(wv, wtqkv + (size_t)(D_ + KV_) * D_, D_, KV_);
    wtrans(wo, wto,  D_, D_);
    wtrans(w1, wt13, D_, HID_);
    wtrans(w3, wt13 + (size_t)HID_ * D_, D_, HID_);
    wtrans(w2, wt2,  HID_, D_);

    // h = LN1(x) (f16)
    ln_kernel<<<S_, 256>>>(x, ln1w, ln1b, h16);
    // fused qkv = h @ [wq|wk|wv]
    gemm(h16, wtqkv, nullptr, qkv, S_, NQKV, D_);
    // RoPE in place on strided q/k
    {
        int tq = S_ * NH_ * 32, tk = S_ * NKV_ * 32;
        rope_kernel<<<(tq + 255) / 256, 256>>>(qkv,       NH_,  NQKV, tq);
        rope_kernel<<<(tk + 255) / 256, 256>>>(qkv + D_,  NKV_, NQKV, tk);
    }
    // attention (strided qkv)
    attn_kernel<<<dim3(S_ / 32, NH_), 256>>>(qkv, qkv + D_, qkv + D_ + KV_, mask, ao16);
    // x1 = x + ao @ wo
    gemm(ao16, wto, x, x1, S_, D_, D_);
    // h2 = LN2(x1) (f16)
    ln_kernel<<<S_, 256>>>(x1, ln2w, ln2b, h216);
    // fused p13 = h2 @ [w1|w3]
    gemm(h216, wt13, nullptr, p13, S_, N13, D_);
    silumul_kernel<<<(S_ * HID_ / 4 + 255) / 256, 256>>>(p13, p1h, S_ * HID_ / 4);
    // out = x1 + (silu(p1)*p3) @ w2
    gemm(p1h, wt2, x1, out, S_, D_, HID_);
}

// round 12
// speedup vs baseline: 1.0285x; 1.0285x over previous
#include <cuda_runtime.h>
#include <cuda_fp16.h>
#include <math.h>
#include <stdint.h>

// ---------------- problem constants ----------------
#define S_    2048
#define D_    2048
#define HID_  5632
#define NH_   32
#define NKV_  8
#define HD_   64
#define KV_   (NKV_*HD_)     // 512
#define NQKV  (D_ + 2*KV_)   // 3072
#define N13   (2*HID_)       // 11264

// ---------------- scratch ----------------
__device__ __half g_h16 [S_*D_];
__device__ float  g_qkv [S_*NQKV];
__device__ __half g_ao16[S_*D_];
__device__ float  g_x1  [S_*D_];
__device__ __half g_h216[S_*D_];
__device__ float  g_p13 [S_*N13];
__device__ __half g_p1h [S_*HID_];
// fp16 transposed weights ([N][K] K-major)
__device__ __half g_wtqkv[NQKV*D_];
__device__ __half g_wto  [D_*D_];
__device__ __half g_wt13 [N13*D_];
__device__ __half g_wt2  [D_*HID_];

// ---------------- helpers ----------------
__device__ __forceinline__ void mma_f16(float* c, const uint32_t* a, uint32_t b0, uint32_t b1) {
    asm volatile(
        "mma.sync.aligned.m16n8k16.row.col.f32.f16.f16.f32 "
        "{%0,%1,%2,%3}, {%4,%5,%6,%7}, {%8,%9}, {%0,%1,%2,%3};"
        : "+f"(c[0]), "+f"(c[1]), "+f"(c[2]), "+f"(c[3])
        : "r"(a[0]), "r"(a[1]), "r"(a[2]), "r"(a[3]), "r"(b0), "r"(b1));
}
__device__ __forceinline__ void ldmatrix4(uint32_t* r, uint32_t addr) {
    asm volatile("ldmatrix.sync.aligned.m8n8.x4.shared.b16 {%0,%1,%2,%3}, [%4];"
                 : "=r"(r[0]), "=r"(r[1]), "=r"(r[2]), "=r"(r[3]) : "r"(addr));
}
__device__ __forceinline__ void cp16(uint32_t s, const void* g) {
    asm volatile("cp.async.cg.shared.global [%0], [%1], 16;" :: "r"(s), "l"(g));
}
__device__ __forceinline__ void cp_commit() { asm volatile("cp.async.commit_group;"); }
__device__ __forceinline__ void cp_wait1()  { asm volatile("cp.async.wait_group 1;"); }

// ---------------- FP16 mma.sync GEMM: CTA 128x128x64, 8 warps (2x4), warp 64x32 ----------------
// C[M,N] = A[M,K](f16) @ Bt[N,K](f16)^T (+res f32).
#define RSTR_B   144                 // bytes per smem row (64 halves + 8 pad)
#define A_BYTES  (128*RSTR_B)        // 18432
#define STG_B    (2*A_BYTES)         // 36864 (A rows 0..127, B rows 0..127)
#define GNS      3
#define GEMM_SMEM (GNS * STG_B)      // 110592 -> 2 CTAs/SM

__global__ __launch_bounds__(256, 2) void gemm_f16_kernel(const __half* __restrict__ A,
                                                          const __half* __restrict__ Bt,
                                                          const float* __restrict__ res,
                                                          float* __restrict__ C,
                                                          int M, int N, int K) {
    extern __shared__ __align__(128) char smem[];
    const uint32_t s0 = (uint32_t)__cvta_generic_to_shared(smem);

    const int tid  = threadIdx.x;
    const int lane = tid & 31;
    const int wid  = tid >> 5;
    const int wm   = wid >> 2;   // 0..1  (64 rows)
    const int wn   = wid & 3;    // 0..3  (32 cols)
    const int bm   = blockIdx.x * 128;
    const int bn   = blockIdx.y * 128;
    const int NT   = K >> 6;

    // ldmatrix per-lane byte offsets within a stage
    uint32_t a_off[4], b_off[2];
    #pragma unroll
    for (int t = 0; t < 4; t++)
        a_off[t] = (uint32_t)(wm * 64 + t * 16 + (lane & 15)) * RSTR_B + (lane >> 4) * 16;
    #pragma unroll
    for (int u = 0; u < 2; u++)
        b_off[u] = A_BYTES + (uint32_t)(wn * 32 + u * 16 + (lane & 7) + ((lane >> 4) * 8)) * RSTR_B
                 + ((lane >> 3) & 1) * 16;

    // global->smem load mapping: 256 threads cover 128 A rows (64B each half) + 128 B rows
    const int arow = tid >> 1;                 // 0..127
    const int acn  = (tid & 1) * 4;            // 4 of 8 16B chunks
    const __half* Ag = A + (size_t)(bm + arow) * K + acn * 8;
    const __half* Bg = Bt + (size_t)(bn + arow) * K + acn * 8;

    auto load_stage = [&](int kt, int s) {
        uint32_t ab = s0 + s * STG_B + arow * RSTR_B + acn * 16;
        const char* ag = (const char*)(Ag + kt * 64);
        #pragma unroll
        for (int i = 0; i < 4; i++) cp16(ab + i * 16, ag + i * 16);
        uint32_t bb = ab + A_BYTES;
        const char* bg = (const char*)(Bg + kt * 64);
        #pragma unroll
        for (int i = 0; i < 4; i++) cp16(bb + i * 16, bg + i * 16);
    };

    float c[4][4][4];
    #pragma unroll
    for (int t = 0; t < 4; t++)
        #pragma unroll
        for (int n = 0; n < 4; n++)
            #pragma unroll
            for (int i = 0; i < 4; i++) c[t][n][i] = 0.f;

    load_stage(0, 0); cp_commit();
    load_stage(1, 1); cp_commit();

    int stg = 0;
    for (int kt = 0; kt < NT; kt++) {
        cp_wait1();
        __syncthreads();
        int nk = kt + 2;
        int nstg = stg + 2; if (nstg >= 3) nstg -= 3;
        if (nk < NT) load_stage(nk, nstg);
        cp_commit();

        const uint32_t sbase = s0 + stg * STG_B;
        #pragma unroll
        for (int s16 = 0; s16 < 4; s16++) {
            uint32_t af[4][4], bf[2][4];
            #pragma unroll
            for (int t = 0; t < 4; t++) ldmatrix4(af[t], sbase + a_off[t] + s16 * 32);
            #pragma unroll
            for (int u = 0; u < 2; u++) ldmatrix4(bf[u], sbase + b_off[u] + s16 * 32);
            #pragma unroll
            for (int t = 0; t < 4; t++)
                #pragma unroll
                for (int u = 0; u < 2; u++) {
                    mma_f16(c[t][2 * u],     af[t], bf[u][0], bf[u][1]);
                    mma_f16(c[t][2 * u + 1], af[t], bf[u][2], bf[u][3]);
                }
        }
        stg++; if (stg >= 3) stg = 0;
    }

    // epilogue: direct global stores
    const int rr = lane >> 2;
    const int cc = lane & 3;
    #pragma unroll
    for (int t = 0; t < 4; t++) {
        int gr = bm + wm * 64 + t * 16 + rr;
        #pragma unroll
        for (int n = 0; n < 4; n++) {
            int gc = bn + wn * 32 + n * 8 + cc * 2;
            size_t i0 = (size_t)gr * N + gc;
            size_t i1 = i0 + (size_t)8 * N;
            float2 v0 = { c[t][n][0], c[t][n][1] };
            float2 v1 = { c[t][n][2], c[t][n][3] };
            if (res) {
                const float2 r0 = *(const float2*)&res[i0];
                const float2 r1 = *(const float2*)&res[i1];
                v0.x += r0.x; v0.y += r0.y;
                v1.x += r1.x; v1.y += r1.y;
            }
            *(float2*)&C[i0] = v0;
            *(float2*)&C[i1] = v1;
        }
    }
}

// ---------------- weight transpose+convert: W[K][N] f32 -> Wt[N][K] f16 ----------------
__global__ __launch_bounds__(256) void transpose_f16_kernel(const float* __restrict__ in,
                                                            __half* __restrict__ out,
                                                            int K, int N) {
    __shared__ float t[32][33];
    int k0 = blockIdx.y * 32, n0 = blockIdx.x * 32;
    int tx = threadIdx.x, ty = threadIdx.y;   // 32 x 8
    #pragma unroll
    for (int j = 0; j < 4; j++)
        t[ty + j * 8][tx] = in[(size_t)(k0 + ty + j * 8) * N + n0 + tx];
    __syncthreads();
    #pragma unroll
    for (int j = 0; j < 4; j++)
        out[(size_t)(n0 + ty + j * 8) * K + k0 + tx] = __float2half_rn(t[tx][ty + j * 8]);
}

// ---------------- LayerNorm: f32 in, f16 out ----------------
__global__ __launch_bounds__(256) void ln_kernel(const float* __restrict__ x,
                                                 const float* __restrict__ w,
                                                 const float* __restrict__ b,
                                                 __half* __restrict__ out) {
    int row = blockIdx.x;
    const float4* xr = (const float4*)(x + (size_t)row * D_);
    float4 v0 = xr[threadIdx.x * 2 + 0];
    float4 v1 = xr[threadIdx.x * 2 + 1];
    float s  = v0.x + v0.y + v0.z + v0.w + v1.x + v1.y + v1.z + v1.w;
    float ss = v0.x*v0.x + v0.y*v0.y + v0.z*v0.z + v0.w*v0.w
             + v1.x*v1.x + v1.y*v1.y + v1.z*v1.z + v1.w*v1.w;
    #pragma unroll
    for (int o = 16; o; o >>= 1) {
        s  += __shfl_xor_sync(0xffffffffu, s,  o);
        ss += __shfl_xor_sync(0xffffffffu, ss, o);
    }
    __shared__ float sm[18];
    int warp = threadIdx.x >> 5, lane = threadIdx.x & 31;
    if (lane == 0) { sm[warp] = s; sm[8 + warp] = ss; }
    __syncthreads();
    if (threadIdx.x == 0) {
        float S1 = 0.f, S2 = 0.f;
        #pragma unroll
        for (int i = 0; i < 8; i++) { S1 += sm[i]; S2 += sm[8 + i]; }
        float mean = S1 / (float)D_;
        float var  = S2 / (float)D_ - mean * mean;
        sm[16] = mean;
        sm[17] = rsqrtf(var + 1e-5f);
    }
    __syncthreads();
    float mean = sm[16], inv = sm[17];
    const float4* wv = (const float4*)w;
    const float4* bv = (const float4*)b;
    __half2* ov = (__half2*)(out + (size_t)row * D_);
    #pragma unroll
    for (int u = 0; u < 2; u++) {
        int idx = threadIdx.x * 2 + u;
        float4 v = (u == 0) ? v0 : v1;
        float4 W = wv[idx], B = bv[idx];
        float o0 = (v.x - mean) * inv * W.x + B.x;
        float o1 = (v.y - mean) * inv * W.y + B.y;
        float o2 = (v.z - mean) * inv * W.z + B.z;
        float o3 = (v.w - mean) * inv * W.w + B.w;
        ov[idx * 2 + 0] = __floats2half2_rn(o0, o1);
        ov[idx * 2 + 1] = __floats2half2_rn(o2, o3);
    }
}

// ---------------- RoPE on strided layout ----------------
__global__ void rope_kernel(float* __restrict__ x, int H, int stride, int total) {
    int i = blockIdx.x * blockDim.x + threadIdx.x;
    if (i >= total) return;
    int p = i & 31;
    int h = (i >> 5) % H;
    int s = i / (32 * H);
    float freq = exp2f(-(float)p * 0.415241011860920f);
    float ang = (float)s * freq;
    float c, sn;
    sincosf(ang, &sn, &c);
    float* base = x + (size_t)s * stride + h * HD_;
    float xr = base[2 * p], xi = base[2 * p + 1];
    base[2 * p]     = xr * c - xi * sn;
    base[2 * p + 1] = xr * sn + xi * c;
}

// ---------------- Flash attention: strided QKV in, f16 out ----------------
__global__ __launch_bounds__(256) void attn_kernel(const float* __restrict__ Q,
                                                   const float* __restrict__ K,
                                                   const float* __restrict__ V,
                                                   const int* __restrict__ mask,
                                                   __half* __restrict__ O) {
    __shared__ float Ks[64][64];
    __shared__ float Vs[64][64];
    __shared__ float bias[64];
    const int h = blockIdx.y;
    const int kvh = h >> 2;            // N_REP = 4
    const int tid = threadIdx.x;
    const int qi = tid >> 3;
    const int lane8 = tid & 7;
    const int qrow = blockIdx.x * 32 + qi;

    float qreg[8];
    const float* qp = Q + (size_t)qrow * NQKV + h * HD_;
    #pragma unroll
    for (int d = 0; d < 8; d++) qreg[d] = qp[lane8 + 8 * d] * 0.125f;

    float m = -INFINITY, l = 0.f;
    float o[8] = {0.f, 0.f, 0.f, 0.f, 0.f, 0.f, 0.f, 0.f};

    const int rr = tid >> 2;
    const int c4 = (tid & 3) * 16;

    for (int kt = 0; kt < S_; kt += 64) {
        const float* kp = K + (size_t)(kt + rr) * NQKV + kvh * HD_ + c4;
        const float* vp = V + (size_t)(kt + rr) * NQKV + kvh * HD_ + c4;
        __syncthreads();
        #pragma unroll
        for (int u = 0; u < 4; u++) {
            *(float4*)&Ks[rr][c4 + u * 4] = *(const float4*)(kp + u * 4);
            *(float4*)&Vs[rr][c4 + u * 4] = *(const float4*)(vp + u * 4);
        }
        if (tid < 64) bias[tid] = (mask[kt + tid] == 0) ? -1e30f : 0.f;
        __syncthreads();

        #pragma unroll 2
        for (int j = 0; j < 64; j++) {
            float sc = 0.f;
            #pragma unroll
            for (int d = 0; d < 8; d++) sc += qreg[d] * Ks[j][lane8 + 8 * d];
            sc += __shfl_xor_sync(0xffffffffu, sc, 1);
            sc += __shfl_xor_sync(0xffffffffu, sc, 2);
            sc += __shfl_xor_sync(0xffffffffu, sc, 4);
            sc += bias[j];
            if (sc > m) {
                float f = __expf(m - sc);
                m = sc;
                l = l * f + 1.f;
                #pragma unroll
                for (int d = 0; d < 8; d++) o[d] = o[d] * f + Vs[j][lane8 + 8 * d];
            } else {
                float p = __expf(sc - m);
                l += p;
                #pragma unroll
                for (int d = 0; d < 8; d++) o[d] += p * Vs[j][lane8 + 8 * d];
            }
        }
    }
    float inv = 1.f / l;
    __half* op = O + (size_t)qrow * D_ + h * HD_;
    #pragma unroll
    for (int d = 0; d < 8; d++) op[lane8 + 8 * d] = __float2half_rn(o[d] * inv);
}

// ---------------- SiLU(p13[:, :HID]) * p13[:, HID:] -> f16 ----------------
__global__ void silumul_kernel(const float* __restrict__ p13, __half* __restrict__ out, int n4) {
    int i = blockIdx.x * blockDim.x + threadIdx.x;
    if (i >= n4) return;
    int row = i / (HID_ / 4);
    int col = (i % (HID_ / 4)) * 4;
    const float4 a = *(const float4*)&p13[(size_t)row * N13 + col];
    const float4 c = *(const float4*)&p13[(size_t)row * N13 + HID_ + col];
    float o0 = a.x / (1.f + __expf(-a.x)) * c.x;
    float o1 = a.y / (1.f + __expf(-a.y)) * c.y;
    float o2 = a.z / (1.f + __expf(-a.z)) * c.z;
    float o3 = a.w / (1.f + __expf(-a.w)) * c.w;
    __half2* op = (__half2*)(out + (size_t)row * HID_ + col);
    op[0] = __floats2half2_rn(o0, o1);
    op[1] = __floats2half2_rn(o2, o3);
}

// ---------------- launch ----------------
static void gemm(const __half* A, const __half* Bt, const float* res, float* C, int M, int N, int K) {
    dim3 grid(M / 128, N / 128);   // x = M tiles (fast-varying) for L2 reuse of B
    gemm_f16_kernel<<<grid, 256, GEMM_SMEM>>>(A, Bt, res, C, M, N, K);
}
static void wtrans(const float* in, __half* out, int K, int N) {
    transpose_f16_kernel<<<dim3(N / 32, K / 32), dim3(32, 8)>>>(in, out, K, N);
}

extern "C" void kernel_launch(void* const* d_in, const int* in_sizes, int n_in,
                              void* d_out, int out_size) {
    const float* x    = (const float*)d_in[0];
    const int*   mask = (const int*)  d_in[1];
    const float* wq   = (const float*)d_in[2];
    const float* wk   = (const float*)d_in[3];
    const float* wv   = (const float*)d_in[4];
    const float* wo   = (const float*)d_in[5];
    const float* w1   = (const float*)d_in[6];
    const float* w2   = (const float*)d_in[7];
    const float* w3   = (const float*)d_in[8];
    const float* ln1w = (const float*)d_in[9];
    const float* ln1b = (const float*)d_in[10];
    const float* ln2w = (const float*)d_in[11];
    const float* ln2b = (const float*)d_in[12];
    float* out = (float*)d_out;

    static bool attr_done = false;
    if (!attr_done) {
        cudaFuncSetAttribute(gemm_f16_kernel, cudaFuncAttributeMaxDynamicSharedMemorySize, GEMM_SMEM);
        attr_done = true;
    }

    __half *h16, *ao16, *h216, *p1h, *wtqkv, *wto, *wt13, *wt2;
    float *qkv, *x1, *p13;
    cudaGetSymbolAddress((void**)&h16,   g_h16);
    cudaGetSymbolAddress((void**)&qkv,   g_qkv);
    cudaGetSymbolAddress((void**)&ao16,  g_ao16);
    cudaGetSymbolAddress((void**)&x1,    g_x1);
    cudaGetSymbolAddress((void**)&h216,  g_h216);
    cudaGetSymbolAddress((void**)&p13,   g_p13);
    cudaGetSymbolAddress((void**)&p1h,   g_p1h);
    cudaGetSymbolAddress((void**)&wtqkv, g_wtqkv);
    cudaGetSymbolAddress((void**)&wto,   g_wto);
    cudaGetSymbolAddress((void**)&wt13,  g_wt13);
    cudaGetSymbolAddress((void**)&wt2,   g_wt2);

    // launch order chosen so launch #5 (ncu -s 5 -c 1) is the big fused QKV GEMM
    ln_kernel<<<S_, 256>>>(x, ln1w, ln1b, h16);                   // 1
    wtrans(wq, wtqkv,                           D_, D_);          // 2
    wtrans(wk, wtqkv + (size_t)D_ * D_,         D_, KV_);         // 3
    wtrans(wv, wtqkv + (size_t)(D_ + KV_) * D_, D_, KV_);         // 4
    gemm(h16, wtqkv, nullptr, qkv, S_, NQKV, D_);                 // 5  <- profiled
    // remaining weight prep
    wtrans(wo, wto,  D_, D_);
    wtrans(w1, wt13, D_, HID_);
    wtrans(w3, wt13 + (size_t)HID_ * D_, D_, HID_);
    wtrans(w2, wt2,  HID_, D_);
    // RoPE in place on strided q/k
    {
        int tq = S_ * NH_ * 32, tk = S_ * NKV_ * 32;
        rope_kernel<<<(tq + 255) / 256, 256>>>(qkv,       NH_,  NQKV, tq);
        rope_kernel<<<(tk + 255) / 256, 256>>>(qkv + D_,  NKV_, NQKV, tk);
    }
    // attention (strided qkv)
    attn_kernel<<<dim3(S_ / 32, NH_), 256>>>(qkv, qkv + D_, qkv + D_ + KV_, mask, ao16);
    // x1 = x + ao @ wo
    gemm(ao16, wto, x, x1, S_, D_, D_);
    // h2 = LN2(x1) (f16)
    ln_kernel<<<S_, 256>>>(x1, ln2w, ln2b, h216);
    // fused p13 = h2 @ [w1|w3]
    gemm(h216, wt13, nullptr, p13, S_, N13, D_);
    silumul_kernel<<<(S_ * HID_ / 4 + 255) / 256, 256>>>(p13, p1h, S_ * HID_ / 4);
    // out = x1 + (silu(p1)*p3) @ w2
    gemm(p1h, wt2, x1, out, S_, D_, HID_);
}